// round 6
// baseline (speedup 1.0000x reference)
#include <cuda_runtime.h>
#include <cuda_fp16.h>
#include <cstdint>

// ============================================================================
// Problem constants
// ============================================================================
#define B_DIM 32768
#define H_DIM 512
#define KTOT  1024   // E + H
#define NTOT  2048   // 4*H

// GEMM tiling
#define BM 128
#define BN 128
#define BK 32              // halves per K-chunk
#define NKIT (KTOT / BK)   // 32
#define STAGES 4
// smem stage: A[128][32] halves @ row stride 80B + B same
#define ROWB 80
#define TILE_BYTES (128 * ROWB)          // 10240
#define STAGE_BYTES (2 * TILE_BYTES)     // 20480
#define PIPE_BYTES (STAGES * STAGE_BYTES) // 81920
// epilogue C stage: 128 x (stride 136 floats)
#define CSTRIDE 136
#define SMEM_TOTAL PIPE_BYTES            // 81920 (epilogue reuses: 128*136*4=69632)

// ============================================================================
// Scratch (device globals — allocation-free)
// ============================================================================
__device__ __half g_A[(size_t)B_DIM * KTOT];   // 64 MB: [x | h0] fp16
__device__ __half g_W[(size_t)NTOT * KTOT];    // 4 MB: gate-interleaved [W_x | W_h]
__device__ float  g_bias[NTOT];                // b_x + b_h, gate-interleaved

// ============================================================================
// PTX helpers (compute_103-safe: no tcgen05)
// ============================================================================
__device__ __forceinline__ uint32_t smem_u32(const void* p) {
    uint32_t a;
    asm("{ .reg .u64 t; cvta.to.shared.u64 t, %1; cvt.u32.u64 %0, t; }" : "=r"(a) : "l"(p));
    return a;
}

__device__ __forceinline__ void cp16(uint32_t saddr, const void* gaddr) {
    asm volatile("cp.async.cg.shared.global [%0], [%1], 16;" :: "r"(saddr), "l"(gaddr) : "memory");
}

__device__ __forceinline__ void ldsm_x4(uint32_t& r0, uint32_t& r1, uint32_t& r2, uint32_t& r3,
                                        uint32_t addr) {
    asm volatile("ldmatrix.sync.aligned.m8n8.x4.shared.b16 {%0,%1,%2,%3}, [%4];"
                 : "=r"(r0), "=r"(r1), "=r"(r2), "=r"(r3) : "r"(addr));
}

__device__ __forceinline__ void mma16816(float& d0, float& d1, float& d2, float& d3,
                                         uint32_t a0, uint32_t a1, uint32_t a2, uint32_t a3,
                                         uint32_t b0, uint32_t b1) {
    asm volatile("mma.sync.aligned.m16n8k16.row.col.f32.f16.f16.f32 "
                 "{%0,%1,%2,%3}, {%4,%5,%6,%7}, {%8,%9}, {%0,%1,%2,%3};"
                 : "+f"(d0), "+f"(d1), "+f"(d2), "+f"(d3)
                 : "r"(a0), "r"(a1), "r"(a2), "r"(a3), "r"(b0), "r"(b1));
}

// ============================================================================
// Pass 1: A = [x | h0] -> fp16
// ============================================================================
__global__ __launch_bounds__(256) void convert_A_kernel(const float* __restrict__ x,
                                                        const float* __restrict__ h0) {
    int g = blockIdx.x * 256 + threadIdx.x;   // group of 4 elements
    int b = g >> 8;                           // 1024/4 = 256 groups per row
    int cg = g & 255;
    const float* src = (cg < 128) ? (x + b * 512 + cg * 4)
                                  : (h0 + b * 512 + (cg - 128) * 4);
    float4 v = *reinterpret_cast<const float4*>(src);
    __half2 lo = __floats2half2_rn(v.x, v.y);
    __half2 hi = __floats2half2_rn(v.z, v.w);
    uint2 u;
    u.x = *reinterpret_cast<const unsigned*>(&lo);
    u.y = *reinterpret_cast<const unsigned*>(&hi);
    *reinterpret_cast<uint2*>(g_A + (size_t)g * 4) = u;
}

// ============================================================================
// Pass 2: W gate-interleaved -> fp16; combined bias
//   dest row r = h*4 + k ; cols [0:512)=W_x[k,h,:], [512:1024)=W_h[k,h,:]
// ============================================================================
__global__ __launch_bounds__(256) void convert_W_kernel(const float* __restrict__ Wx,
                                                        const float* __restrict__ Wh,
                                                        const float* __restrict__ bx,
                                                        const float* __restrict__ bh) {
    int g = blockIdx.x * 256 + threadIdx.x;
    int r = g >> 8;           // 0..2047
    int cg = g & 255;
    int k = r & 3;
    int h = r >> 2;
    int c = cg * 4;
    const float* src = (cg < 128) ? (Wx + (k * 512 + h) * 512 + c)
                                  : (Wh + (k * 512 + h) * 512 + (c - 512));
    float4 v = *reinterpret_cast<const float4*>(src);
    __half2 lo = __floats2half2_rn(v.x, v.y);
    __half2 hi = __floats2half2_rn(v.z, v.w);
    uint2 u;
    u.x = *reinterpret_cast<const unsigned*>(&lo);
    u.y = *reinterpret_cast<const unsigned*>(&hi);
    *reinterpret_cast<uint2*>(g_W + (size_t)g * 4) = u;

    if (blockIdx.x == 0) {
        for (int rr = threadIdx.x; rr < NTOT; rr += 256) {
            int kk = rr & 3, hh = rr >> 2;
            g_bias[rr] = bx[kk * 512 + hh] + bh[kk * 512 + hh];
        }
    }
}

// ============================================================================
// Pass 3: fused GEMM (mma.sync m16n8k16 f16->f32) + LSTM epilogue
//   CTA 128x128, 8 warps = 2(M) x 4(N), warp tile 64x32
// ============================================================================
__device__ __forceinline__ void stage_tile(uint32_t sb, int buf, int m0, int n0, int k0, int tid) {
    const uint32_t abase = sb + buf * STAGE_BYTES;
    const uint32_t bbase = abase + TILE_BYTES;
#pragma unroll
    for (int j = 0; j < 2; j++) {
        int i = tid + j * 256;       // 0..511 16B-chunk slot
        int row = i >> 2;            // 4 x 16B per 64B data row
        int c4 = i & 3;
        uint32_t dst_off = (uint32_t)(row * ROWB + c4 * 16);
        cp16(abase + dst_off, g_A + (size_t)(m0 + row) * KTOT + k0 + c4 * 8);
        cp16(bbase + dst_off, g_W + (size_t)(n0 + row) * KTOT + k0 + c4 * 8);
    }
}

__global__ __launch_bounds__(256, 2) void lstm_gemm_kernel(const float* __restrict__ c0,
                                                           float* __restrict__ out) {
    extern __shared__ char smem[];
    const uint32_t sb = smem_u32(smem);
    const int tid = threadIdx.x;
    const int wid = tid >> 5;
    const int lane = tid & 31;
    const int n0 = blockIdx.x * BN;   // N fastest -> CTAs sharing A run together
    const int m0 = blockIdx.y * BM;

    const int warpM = wid & 1;        // 0..1 (64 rows each)
    const int warpN = wid >> 1;       // 0..3 (32 cols each)

    float acc[4][4][4];               // [mt][nt][reg]
#pragma unroll
    for (int a = 0; a < 4; a++)
#pragma unroll
        for (int b = 0; b < 4; b++)
#pragma unroll
            for (int r = 0; r < 4; r++) acc[a][b][r] = 0.0f;

    // ldmatrix per-lane offsets (within a stage buffer)
    // A: row = warpM*64 + mt*16 + (lane&15); byte = ((lane>>4)&1)*16 + ks*32
    const uint32_t a_lane_off = (uint32_t)((warpM * 64 + (lane & 15)) * ROWB + ((lane >> 4) & 1) * 16);
    // B: row = warpN*32 + ntp*16 + (lane&7) + ((lane>>4)&1)*8 ; byte = ((lane>>3)&1)*16 + ks*32
    const uint32_t b_lane_off = (uint32_t)((warpN * 32 + (lane & 7) + ((lane >> 4) & 1) * 8) * ROWB
                                           + ((lane >> 3) & 1) * 16);

    // Prologue: stage buffers 0..2
#pragma unroll
    for (int s = 0; s < STAGES - 1; s++) {
        stage_tile(sb, s, m0, n0, s * BK, tid);
        asm volatile("cp.async.commit_group;" ::: "memory");
    }

#pragma unroll 1
    for (int kt = 0; kt < NKIT; kt++) {
        asm volatile("cp.async.wait_group %0;" :: "n"(STAGES - 2) : "memory");
        __syncthreads();

        // Issue next stage (overwrites buffer computed in iter kt-1)
        if (kt + STAGES - 1 < NKIT)
            stage_tile(sb, (kt + STAGES - 1) & (STAGES - 1), m0, n0, (kt + STAGES - 1) * BK, tid);
        asm volatile("cp.async.commit_group;" ::: "memory");

        // Compute on buffer kt%STAGES
        const uint32_t abase = sb + (kt & (STAGES - 1)) * STAGE_BYTES;
        const uint32_t bbase = abase + TILE_BYTES;
#pragma unroll
        for (int ks = 0; ks < 2; ks++) {
            uint32_t a[4][4];
#pragma unroll
            for (int mt = 0; mt < 4; mt++)
                ldsm_x4(a[mt][0], a[mt][1], a[mt][2], a[mt][3],
                        abase + a_lane_off + (uint32_t)(mt * 16 * ROWB) + (uint32_t)(ks * 32));
            uint32_t b[4][2];
#pragma unroll
            for (int ntp = 0; ntp < 2; ntp++) {
                uint32_t r0, r1, r2, r3;
                ldsm_x4(r0, r1, r2, r3,
                        bbase + b_lane_off + (uint32_t)(ntp * 16 * ROWB) + (uint32_t)(ks * 32));
                b[2 * ntp + 0][0] = r0; b[2 * ntp + 0][1] = r1;
                b[2 * ntp + 1][0] = r2; b[2 * ntp + 1][1] = r3;
            }
#pragma unroll
            for (int mt = 0; mt < 4; mt++)
#pragma unroll
                for (int nt = 0; nt < 4; nt++)
                    mma16816(acc[mt][nt][0], acc[mt][nt][1], acc[mt][nt][2], acc[mt][nt][3],
                             a[mt][0], a[mt][1], a[mt][2], a[mt][3],
                             b[nt][0], b[nt][1]);
        }
        __syncthreads();  // all warps done with buffer before it is refilled next iter
    }

    // -------- Epilogue: stage C through smem, fused LSTM gates --------
    float* csm = reinterpret_cast<float*>(smem);
    {
        const int rbase = warpM * 64 + (lane >> 2);
        const int cbase = warpN * 32 + 2 * (lane & 3);
#pragma unroll
        for (int mt = 0; mt < 4; mt++) {
#pragma unroll
            for (int nt = 0; nt < 4; nt++) {
                int r = rbase + mt * 16;
                int c = cbase + nt * 8;
                *reinterpret_cast<float2*>(csm + r * CSTRIDE + c) =
                    make_float2(acc[mt][nt][0], acc[mt][nt][1]);
                *reinterpret_cast<float2*>(csm + (r + 8) * CSTRIDE + c) =
                    make_float2(acc[mt][nt][2], acc[mt][nt][3]);
            }
        }
    }
    __syncthreads();

    {
        const int hbase = n0 >> 2;                  // 32 hidden units per CTA tile
        const int h = hbase + lane;                 // unit handled by this lane
        float4 bias = *reinterpret_cast<const float4*>(g_bias + n0 + lane * 4);
#pragma unroll 4
        for (int it = 0; it < 16; it++) {
            int row = (tid >> 5) + 8 * it;          // 8 warps x 16 iters = 128 rows
            int b = m0 + row;
            float4 z = *reinterpret_cast<const float4*>(csm + row * CSTRIDE + lane * 4);
            float zi = z.x + bias.x;
            float zf = z.y + bias.y;
            float zo = z.z + bias.z;
            float zg = z.w + bias.w;
            float ig = 1.0f / (1.0f + __expf(-zi));
            float fg = 1.0f / (1.0f + __expf(-zf));
            float og = 1.0f / (1.0f + __expf(-zo));
            float gg = tanhf(zg);
            float c1 = fg * __ldg(c0 + (size_t)b * H_DIM + h) + ig * gg;
            float h1 = og * tanhf(c1);
            out[(size_t)b * H_DIM + h] = h1;                                  // h1
            out[(size_t)B_DIM * H_DIM + (size_t)b * H_DIM + h] = c1;          // c1
        }
    }
}

// ============================================================================
// kernel_launch
// ============================================================================
extern "C" void kernel_launch(void* const* d_in, const int* in_sizes, int n_in,
                              void* d_out, int out_size) {
    (void)in_sizes; (void)n_in; (void)out_size;
    const float* x  = (const float*)d_in[0];
    const float* h0 = (const float*)d_in[1];
    const float* c0 = (const float*)d_in[2];
    const float* Wx = (const float*)d_in[3];
    const float* bx = (const float*)d_in[4];
    const float* Wh = (const float*)d_in[5];
    const float* bh = (const float*)d_in[6];
    float* out = (float*)d_out;

    convert_A_kernel<<<(B_DIM * KTOT) / (4 * 256), 256>>>(x, h0);
    convert_W_kernel<<<(NTOT * KTOT) / (4 * 256), 256>>>(Wx, Wh, bx, bh);

    cudaFuncSetAttribute(lstm_gemm_kernel, cudaFuncAttributeMaxDynamicSharedMemorySize, SMEM_TOTAL);
    dim3 grid(NTOT / BN, B_DIM / BM);   // (16, 256), N fastest
    lstm_gemm_kernel<<<grid, 256, SMEM_TOTAL>>>(c0, out);
}

// round 7
// speedup vs baseline: 1.0173x; 1.0173x over previous
#include <cuda_runtime.h>
#include <cuda_fp16.h>
#include <cstdint>

// ============================================================================
// Problem constants
// ============================================================================
#define B_DIM 32768
#define H_DIM 512
#define KTOT  1024   // E + H
#define NTOT  2048   // 4*H

// GEMM tiling
#define BM 128
#define BN 128
#define BK 64              // halves per K-chunk
#define NKIT (KTOT / BK)   // 16
#define STAGES 3
#define ROWB 144           // 128B data + 16B pad per row
#define TILE_BYTES (128 * ROWB)           // 18432
#define STAGE_BYTES (2 * TILE_BYTES)      // 36864
#define SMEM_TOTAL (STAGES * STAGE_BYTES) // 110592 -> 2 CTA/SM
// epilogue C stage: 128 rows x 132 floats (conflict-free, 16B aligned rows)
#define CSTRIDE 132

#define NTHREADS 512

// ============================================================================
// Scratch (device globals — allocation-free)
// ============================================================================
__device__ __half g_A[(size_t)B_DIM * KTOT];   // 64 MB: [x | h0] fp16
__device__ __half g_W[(size_t)NTOT * KTOT];    // 4 MB: gate-interleaved [W_x | W_h]
__device__ float  g_bias[NTOT];                // b_x + b_h, gate-interleaved

// ============================================================================
// PTX helpers (compute_103-safe: legacy mma path only)
// ============================================================================
__device__ __forceinline__ uint32_t smem_u32(const void* p) {
    uint32_t a;
    asm("{ .reg .u64 t; cvta.to.shared.u64 t, %1; cvt.u32.u64 %0, t; }" : "=r"(a) : "l"(p));
    return a;
}

__device__ __forceinline__ void cp16(uint32_t saddr, const void* gaddr) {
    asm volatile("cp.async.cg.shared.global [%0], [%1], 16;" :: "r"(saddr), "l"(gaddr) : "memory");
}

__device__ __forceinline__ void ldsm_x4(uint32_t& r0, uint32_t& r1, uint32_t& r2, uint32_t& r3,
                                        uint32_t addr) {
    asm volatile("ldmatrix.sync.aligned.m8n8.x4.shared.b16 {%0,%1,%2,%3}, [%4];"
                 : "=r"(r0), "=r"(r1), "=r"(r2), "=r"(r3) : "r"(addr));
}

// f16-accumulate mma (the hot instruction this round)
__device__ __forceinline__ void mma16816_f16(uint32_t& d0, uint32_t& d1,
                                             uint32_t a0, uint32_t a1, uint32_t a2, uint32_t a3,
                                             uint32_t b0, uint32_t b1) {
    asm volatile("mma.sync.aligned.m16n8k16.row.col.f16.f16.f16.f16 "
                 "{%0,%1}, {%2,%3,%4,%5}, {%6,%7}, {%0,%1};"
                 : "+r"(d0), "+r"(d1)
                 : "r"(a0), "r"(a1), "r"(a2), "r"(a3), "r"(b0), "r"(b1));
}

// ============================================================================
// Pass 1: A = [x | h0] -> fp16
// ============================================================================
__global__ __launch_bounds__(256) void convert_A_kernel(const float* __restrict__ x,
                                                        const float* __restrict__ h0) {
    int g = blockIdx.x * 256 + threadIdx.x;   // group of 4 elements
    int b = g >> 8;                           // 1024/4 = 256 groups per row
    int cg = g & 255;
    const float* src = (cg < 128) ? (x + b * 512 + cg * 4)
                                  : (h0 + b * 512 + (cg - 128) * 4);
    float4 v = *reinterpret_cast<const float4*>(src);
    __half2 lo = __floats2half2_rn(v.x, v.y);
    __half2 hi = __floats2half2_rn(v.z, v.w);
    uint2 u;
    u.x = *reinterpret_cast<const unsigned*>(&lo);
    u.y = *reinterpret_cast<const unsigned*>(&hi);
    *reinterpret_cast<uint2*>(g_A + (size_t)g * 4) = u;
}

// ============================================================================
// Pass 2: W gate-interleaved -> fp16; combined bias
//   dest row r = h*4 + k ; cols [0:512)=W_x[k,h,:], [512:1024)=W_h[k,h,:]
// ============================================================================
__global__ __launch_bounds__(256) void convert_W_kernel(const float* __restrict__ Wx,
                                                        const float* __restrict__ Wh,
                                                        const float* __restrict__ bx,
                                                        const float* __restrict__ bh) {
    int g = blockIdx.x * 256 + threadIdx.x;
    int r = g >> 8;           // 0..2047
    int cg = g & 255;
    int k = r & 3;
    int h = r >> 2;
    int c = cg * 4;
    const float* src = (cg < 128) ? (Wx + (k * 512 + h) * 512 + c)
                                  : (Wh + (k * 512 + h) * 512 + (c - 512));
    float4 v = *reinterpret_cast<const float4*>(src);
    __half2 lo = __floats2half2_rn(v.x, v.y);
    __half2 hi = __floats2half2_rn(v.z, v.w);
    uint2 u;
    u.x = *reinterpret_cast<const unsigned*>(&lo);
    u.y = *reinterpret_cast<const unsigned*>(&hi);
    *reinterpret_cast<uint2*>(g_W + (size_t)g * 4) = u;

    if (blockIdx.x == 0) {
        for (int rr = threadIdx.x; rr < NTOT; rr += 256) {
            int kk = rr & 3, hh = rr >> 2;
            g_bias[rr] = bx[kk * 512 + hh] + bh[kk * 512 + hh];
        }
    }
}

// ============================================================================
// Pass 3: fused GEMM (mma.sync f16-accumulate + per-K64 fp32 promotion)
//   CTA 128x128, 16 warps = 4(M) x 4(N), warp tile 32x32
// ============================================================================
__device__ __forceinline__ void stage_tile(uint32_t sb, int buf, int m0, int n0, int k0, int tid) {
    const uint32_t abase = sb + buf * STAGE_BYTES;
    const uint32_t bbase = abase + TILE_BYTES;
#pragma unroll
    for (int j = 0; j < 2; j++) {
        int i = tid + j * NTHREADS;   // 0..1023 16B-chunk slot (128 rows x 8 chunks)
        int row = i >> 3;
        int c8 = i & 7;
        uint32_t dst_off = (uint32_t)(row * ROWB + c8 * 16);
        cp16(abase + dst_off, g_A + (size_t)(m0 + row) * KTOT + k0 + c8 * 8);
        cp16(bbase + dst_off, g_W + (size_t)(n0 + row) * KTOT + k0 + c8 * 8);
    }
}

__global__ __launch_bounds__(NTHREADS, 2) void lstm_gemm_kernel(const float* __restrict__ c0,
                                                                float* __restrict__ out) {
    extern __shared__ char smem[];
    const uint32_t sb = smem_u32(smem);
    const int tid = threadIdx.x;
    const int wid = tid >> 5;
    const int lane = tid & 31;
    const int n0 = blockIdx.x * BN;   // N fastest -> CTAs sharing A run together (W stays in L2)
    const int m0 = blockIdx.y * BM;

    const int warpM = wid & 3;        // 4 M-warps of 32 rows
    const int warpN = wid >> 2;       // 4 N-warps of 32 cols

    float acc[2][4][4];               // fp32 masters [mt][nt][reg]
#pragma unroll
    for (int a = 0; a < 2; a++)
#pragma unroll
        for (int b = 0; b < 4; b++)
#pragma unroll
            for (int r = 0; r < 4; r++) acc[a][b][r] = 0.0f;

    // ldmatrix per-lane base offsets (within a stage buffer)
    const uint32_t a_lane_off = (uint32_t)((warpM * 32 + (lane & 15)) * ROWB + ((lane >> 4) & 1) * 16);
    const uint32_t b_lane_off = (uint32_t)((warpN * 32 + (lane & 7) + ((lane >> 4) & 1) * 8) * ROWB
                                           + ((lane >> 3) & 1) * 16);

    // Prologue: stage buffers 0,1
    stage_tile(sb, 0, m0, n0, 0, tid);
    asm volatile("cp.async.commit_group;" ::: "memory");
    stage_tile(sb, 1, m0, n0, BK, tid);
    asm volatile("cp.async.commit_group;" ::: "memory");

    int cbuf = 0, sbuf = 2;
#pragma unroll 1
    for (int kt = 0; kt < NKIT; kt++) {
        asm volatile("cp.async.wait_group 1;" ::: "memory");
        __syncthreads();   // also guarantees last iter's reads of sbuf are done

        if (kt + 2 < NKIT)
            stage_tile(sb, sbuf, m0, n0, (kt + 2) * BK, tid);
        asm volatile("cp.async.commit_group;" ::: "memory");

        const uint32_t abase = sb + cbuf * STAGE_BYTES;
        const uint32_t bbase = abase + TILE_BYTES;

        // f16 accumulators for this K=64 chunk
        uint32_t dacc[2][4][2];
#pragma unroll
        for (int mt = 0; mt < 2; mt++)
#pragma unroll
            for (int nt = 0; nt < 4; nt++) { dacc[mt][nt][0] = 0u; dacc[mt][nt][1] = 0u; }

#pragma unroll
        for (int ks = 0; ks < 4; ks++) {
            uint32_t a[2][4];
#pragma unroll
            for (int mt = 0; mt < 2; mt++)
                ldsm_x4(a[mt][0], a[mt][1], a[mt][2], a[mt][3],
                        abase + a_lane_off + (uint32_t)(mt * 16 * ROWB) + (uint32_t)(ks * 32));
            uint32_t b[4][2];
#pragma unroll
            for (int ntp = 0; ntp < 2; ntp++) {
                uint32_t r0, r1, r2, r3;
                ldsm_x4(r0, r1, r2, r3,
                        bbase + b_lane_off + (uint32_t)(ntp * 16 * ROWB) + (uint32_t)(ks * 32));
                b[2 * ntp + 0][0] = r0; b[2 * ntp + 0][1] = r1;
                b[2 * ntp + 1][0] = r2; b[2 * ntp + 1][1] = r3;
            }
#pragma unroll
            for (int mt = 0; mt < 2; mt++)
#pragma unroll
                for (int nt = 0; nt < 4; nt++)
                    mma16816_f16(dacc[mt][nt][0], dacc[mt][nt][1],
                                 a[mt][0], a[mt][1], a[mt][2], a[mt][3],
                                 b[nt][0], b[nt][1]);
        }

        // Promote K=64 chunk into fp32 masters
#pragma unroll
        for (int mt = 0; mt < 2; mt++)
#pragma unroll
            for (int nt = 0; nt < 4; nt++) {
                float2 f0 = __half22float2(*reinterpret_cast<__half2*>(&dacc[mt][nt][0]));
                float2 f1 = __half22float2(*reinterpret_cast<__half2*>(&dacc[mt][nt][1]));
                acc[mt][nt][0] += f0.x; acc[mt][nt][1] += f0.y;
                acc[mt][nt][2] += f1.x; acc[mt][nt][3] += f1.y;
            }

        cbuf = (cbuf == STAGES - 1) ? 0 : cbuf + 1;
        sbuf = (sbuf == STAGES - 1) ? 0 : sbuf + 1;
    }

    // -------- Epilogue: stage C through smem, fused LSTM gates --------
    __syncthreads();   // all warps done reading stage buffers before reuse as csm
    float* csm = reinterpret_cast<float*>(smem);
    {
        const int rbase = warpM * 32 + (lane >> 2);
        const int cbase = warpN * 32 + 2 * (lane & 3);
#pragma unroll
        for (int mt = 0; mt < 2; mt++) {
#pragma unroll
            for (int nt = 0; nt < 4; nt++) {
                int r = rbase + mt * 16;
                int c = cbase + nt * 8;
                *reinterpret_cast<float2*>(csm + r * CSTRIDE + c) =
                    make_float2(acc[mt][nt][0], acc[mt][nt][1]);
                *reinterpret_cast<float2*>(csm + (r + 8) * CSTRIDE + c) =
                    make_float2(acc[mt][nt][2], acc[mt][nt][3]);
            }
        }
    }
    __syncthreads();

    {
        const int hbase = n0 >> 2;                  // 32 hidden units per CTA tile
        const int h = hbase + lane;                 // unit handled by this lane
        float4 bias = *reinterpret_cast<const float4*>(g_bias + n0 + lane * 4);
#pragma unroll 4
        for (int it = 0; it < 8; it++) {
            int row = wid + 16 * it;                // 16 warps x 8 iters = 128 rows
            int b = m0 + row;
            float4 z = *reinterpret_cast<const float4*>(csm + row * CSTRIDE + lane * 4);
            float zi = z.x + bias.x;
            float zf = z.y + bias.y;
            float zo = z.z + bias.z;
            float zg = z.w + bias.w;
            float ig = 1.0f / (1.0f + __expf(-zi));
            float fg = 1.0f / (1.0f + __expf(-zf));
            float og = 1.0f / (1.0f + __expf(-zo));
            float gg = tanhf(zg);
            float c1 = fg * __ldg(c0 + (size_t)b * H_DIM + h) + ig * gg;
            float h1 = og * tanhf(c1);
            out[(size_t)b * H_DIM + h] = h1;                                  // h1
            out[(size_t)B_DIM * H_DIM + (size_t)b * H_DIM + h] = c1;          // c1
        }
    }
}

// ============================================================================
// kernel_launch
// ============================================================================
extern "C" void kernel_launch(void* const* d_in, const int* in_sizes, int n_in,
                              void* d_out, int out_size) {
    (void)in_sizes; (void)n_in; (void)out_size;
    const float* x  = (const float*)d_in[0];
    const float* h0 = (const float*)d_in[1];
    const float* c0 = (const float*)d_in[2];
    const float* Wx = (const float*)d_in[3];
    const float* bx = (const float*)d_in[4];
    const float* Wh = (const float*)d_in[5];
    const float* bh = (const float*)d_in[6];
    float* out = (float*)d_out;

    convert_A_kernel<<<(B_DIM * KTOT) / (4 * 256), 256>>>(x, h0);
    convert_W_kernel<<<(NTOT * KTOT) / (4 * 256), 256>>>(Wx, Wh, bx, bh);

    cudaFuncSetAttribute(lstm_gemm_kernel, cudaFuncAttributeMaxDynamicSharedMemorySize, SMEM_TOTAL);
    dim3 grid(NTOT / BN, B_DIM / BM);   // (16, 256), N fastest
    lstm_gemm_kernel<<<grid, NTHREADS, SMEM_TOTAL>>>(c0, out);
}